// round 1
// baseline (speedup 1.0000x reference)
#include <cuda_runtime.h>
#include <math.h>

#define T_ 2048
#define D_ 1024
#define I_ 2048
#define E_ 8

// ---------------- device scratch (static, no allocations) ----------------
__device__ int   g_cnt[E_];            // tokens routed to each expert
__device__ int   g_off[E_];            // exclusive prefix of counts
__device__ int   g_tok[E_ * T_];       // per-expert token lists (segmented by e*T_)
__device__ float g_scr[E_ * T_];       // matching routing probability
__device__ float g_h[(size_t)2 * T_ * I_];  // 4096 x 2048 fp32 = 32 MB intermediate

// ---------------- zero output + counters ----------------
__global__ void k_zero(float* __restrict__ out) {
    int idx = blockIdx.x * blockDim.x + threadIdx.x;  // 524288 threads, one float4 each
    ((float4*)out)[idx] = make_float4(0.f, 0.f, 0.f, 0.f);
    if (idx < E_) g_cnt[idx] = 0;
}

// ---------------- gating: logits -> softmax -> top-2 -> expert lists ----------------
__global__ void k_gate(const float* __restrict__ x, const float* __restrict__ gw) {
    const int t = blockIdx.x;
    const float* xr = x + (size_t)t * D_;

    float p[E_];
#pragma unroll
    for (int e = 0; e < E_; e++) p[e] = 0.f;

    for (int d = threadIdx.x; d < D_; d += blockDim.x) {
        float xv = xr[d];
#pragma unroll
        for (int e = 0; e < E_; e++) p[e] += xv * gw[e * D_ + d];
    }
#pragma unroll
    for (int o = 16; o; o >>= 1) {
#pragma unroll
        for (int e = 0; e < E_; e++) p[e] += __shfl_down_sync(0xffffffffu, p[e], o);
    }

    __shared__ float sm[E_][8];
    const int w = threadIdx.x >> 5, ln = threadIdx.x & 31;
    if (ln == 0) {
#pragma unroll
        for (int e = 0; e < E_; e++) sm[e][w] = p[e];
    }
    __syncthreads();

    if (threadIdx.x == 0) {
        float lg[E_];
#pragma unroll
        for (int e = 0; e < E_; e++) {
            float s = 0.f;
#pragma unroll
            for (int ww = 0; ww < 8; ww++) s += sm[e][ww];
            lg[e] = s;
        }
        float mx = lg[0];
#pragma unroll
        for (int e = 1; e < E_; e++) mx = fmaxf(mx, lg[e]);
        float pr[E_]; float den = 0.f;
#pragma unroll
        for (int e = 0; e < E_; e++) { pr[e] = expf(lg[e] - mx); den += pr[e]; }
        float inv = 1.f / den;
#pragma unroll
        for (int e = 0; e < E_; e++) pr[e] *= inv;

        // top-2, first-occurrence tie-break (matches jax.lax.top_k)
        int e1 = 0;
#pragma unroll
        for (int e = 1; e < E_; e++) if (pr[e] > pr[e1]) e1 = e;
        int e2 = (e1 == 0) ? 1 : 0;
#pragma unroll
        for (int e = 0; e < E_; e++) if (e != e1 && pr[e] > pr[e2]) e2 = e;

        int i1 = atomicAdd(&g_cnt[e1], 1);
        g_tok[e1 * T_ + i1] = t; g_scr[e1 * T_ + i1] = pr[e1];
        int i2 = atomicAdd(&g_cnt[e2], 1);
        g_tok[e2 * T_ + i2] = t; g_scr[e2 * T_ + i2] = pr[e2];
    }
}

// ---------------- prefix sum of expert counts ----------------
__global__ void k_prefix() {
    if (threadIdx.x == 0) {
        int s = 0;
#pragma unroll
        for (int e = 0; e < E_; e++) { g_off[e] = s; s += g_cnt[e]; }
    }
}

// ---------------- GEMM1: h = silu(X_gathered @ w1[e]), 64x64x16 fp32 tiles ----------------
__global__ __launch_bounds__(256) void k_ffn1(const float* __restrict__ x,
                                              const float* __restrict__ w1) {
    const int e    = blockIdx.z;
    const int cnt  = g_cnt[e];
    const int row0 = blockIdx.y * 64;
    if (row0 >= cnt) return;
    const int n0  = blockIdx.x * 64;
    const int off = g_off[e];
    const float* B = w1 + (size_t)e * D_ * I_;

    __shared__ float As[16][68];   // padded to dodge bank conflicts on transposed store
    __shared__ float Bs[16][64];

    const int tid  = threadIdx.x;
    const int arow = tid >> 2, aseg = tid & 3;    // A tile: 64 rows x 16 k, float4/thread
    const int brow = tid >> 4, bseg = tid & 15;   // B tile: 16 k x 64 n, float4/thread
    const int ty   = tid >> 4, tx   = tid & 15;

    int gr  = row0 + arow;
    int grc = (gr < cnt) ? gr : row0;             // clamp OOB rows to a valid slot
    const int tokA = g_tok[e * T_ + grc];
    const float* aptr = x + (size_t)tokA * D_ + aseg * 4;
    const float* bptr = B + (size_t)brow * I_ + n0 + bseg * 4;

    float acc[4][4];
#pragma unroll
    for (int i = 0; i < 4; i++)
#pragma unroll
        for (int j = 0; j < 4; j++) acc[i][j] = 0.f;

    for (int k0 = 0; k0 < D_; k0 += 16) {
        float4 av = *(const float4*)(aptr + k0);
        float4 bv = *(const float4*)(bptr + (size_t)k0 * I_);
        As[aseg * 4 + 0][arow] = av.x;
        As[aseg * 4 + 1][arow] = av.y;
        As[aseg * 4 + 2][arow] = av.z;
        As[aseg * 4 + 3][arow] = av.w;
        *(float4*)&Bs[brow][bseg * 4] = bv;
        __syncthreads();
#pragma unroll
        for (int k = 0; k < 16; k++) {
            float4 a = *(const float4*)&As[k][ty * 4];
            float4 b = *(const float4*)&Bs[k][tx * 4];
            float ar[4] = {a.x, a.y, a.z, a.w};
            float br[4] = {b.x, b.y, b.z, b.w};
#pragma unroll
            for (int r = 0; r < 4; r++)
#pragma unroll
                for (int c = 0; c < 4; c++) acc[r][c] += ar[r] * br[c];
        }
        __syncthreads();
    }

#pragma unroll
    for (int r = 0; r < 4; r++) {
        int row = row0 + ty * 4 + r;
        if (row < cnt) {
            float* hp = g_h + (size_t)(off + row) * I_ + n0 + tx * 4;
#pragma unroll
            for (int c = 0; c < 4; c++) {
                float v = acc[r][c];
                hp[c] = v / (1.f + expf(-v));   // silu
            }
        }
    }
}

// ---------------- GEMM2: out[tok] += score * (h @ w2[e]) ----------------
__global__ __launch_bounds__(256) void k_ffn2(const float* __restrict__ w2,
                                              float* __restrict__ out) {
    const int e    = blockIdx.z;
    const int cnt  = g_cnt[e];
    const int row0 = blockIdx.y * 64;
    if (row0 >= cnt) return;
    const int n0  = blockIdx.x * 64;
    const int off = g_off[e];
    const float* B = w2 + (size_t)e * I_ * D_;
    const float* A = g_h + (size_t)off * I_;

    __shared__ float As[16][68];
    __shared__ float Bs[16][64];

    const int tid  = threadIdx.x;
    const int arow = tid >> 2, aseg = tid & 3;
    const int brow = tid >> 4, bseg = tid & 15;
    const int ty   = tid >> 4, tx   = tid & 15;

    int gr  = row0 + arow;
    int grc = (gr < cnt) ? gr : row0;
    const float* aptr = A + (size_t)grc * I_ + aseg * 4;
    const float* bptr = B + (size_t)brow * D_ + n0 + bseg * 4;

    float acc[4][4];
#pragma unroll
    for (int i = 0; i < 4; i++)
#pragma unroll
        for (int j = 0; j < 4; j++) acc[i][j] = 0.f;

    for (int k0 = 0; k0 < I_; k0 += 16) {
        float4 av = *(const float4*)(aptr + k0);
        float4 bv = *(const float4*)(bptr + (size_t)k0 * D_);
        As[aseg * 4 + 0][arow] = av.x;
        As[aseg * 4 + 1][arow] = av.y;
        As[aseg * 4 + 2][arow] = av.z;
        As[aseg * 4 + 3][arow] = av.w;
        *(float4*)&Bs[brow][bseg * 4] = bv;
        __syncthreads();
#pragma unroll
        for (int k = 0; k < 16; k++) {
            float4 a = *(const float4*)&As[k][ty * 4];
            float4 b = *(const float4*)&Bs[k][tx * 4];
            float ar[4] = {a.x, a.y, a.z, a.w};
            float br[4] = {b.x, b.y, b.z, b.w};
#pragma unroll
            for (int r = 0; r < 4; r++)
#pragma unroll
                for (int c = 0; c < 4; c++) acc[r][c] += ar[r] * br[c];
        }
        __syncthreads();
    }

#pragma unroll
    for (int r = 0; r < 4; r++) {
        int row = row0 + ty * 4 + r;
        if (row < cnt) {
            const int   tok = g_tok[e * T_ + row];
            const float s   = g_scr[e * T_ + row];
            float* op = out + (size_t)tok * D_ + n0 + tx * 4;
#pragma unroll
            for (int c = 0; c < 4; c++) atomicAdd(&op[c], s * acc[r][c]);
        }
    }
}

// ---------------- launch ----------------
extern "C" void kernel_launch(void* const* d_in, const int* in_sizes, int n_in,
                              void* d_out, int out_size) {
    const float* x  = (const float*)d_in[0];  // hidden_states (T, D)
    const float* gw = (const float*)d_in[1];  // gate_w (E, D)
    const float* w1 = (const float*)d_in[2];  // w1 (E, D, I)
    const float* w2 = (const float*)d_in[3];  // w2 (E, I, D)
    float* out = (float*)d_out;               // (T, D) fp32

    k_zero<<<(T_ * D_ / 4) / 256, 256>>>(out);
    k_gate<<<T_, 256>>>(x, gw);
    k_prefix<<<1, 32>>>();
    k_ffn1<<<dim3(I_ / 64, T_ / 64, E_), 256>>>(x, w1);
    k_ffn2<<<dim3(D_ / 64, T_ / 64, E_), 256>>>(w2, out);
}

// round 2
// speedup vs baseline: 3.1600x; 3.1600x over previous
#include <cuda_runtime.h>
#include <math.h>
#include <stdint.h>

#define T_ 2048
#define D_ 1024
#define I_ 2048
#define E_ 8

// ---------------- device scratch ----------------
__device__ int   g_cnt[E_];
__device__ int   g_off[E_];
__device__ int   g_tok[E_ * T_];
__device__ float g_scr[E_ * T_];
__device__ float g_h[(size_t)2 * T_ * I_];   // 4096 x 2048 fp32

// ---------------- helpers ----------------
__device__ __forceinline__ unsigned f2tf(float f) {
    unsigned u; asm("cvt.rna.tf32.f32 %0, %1;" : "=r"(u) : "f"(f)); return u;
}
__device__ __forceinline__ void mma_tf32(float* c, const unsigned* a, const unsigned* b) {
    asm volatile("mma.sync.aligned.m16n8k8.row.col.f32.tf32.tf32.f32 "
                 "{%0,%1,%2,%3}, {%4,%5,%6,%7}, {%8,%9}, {%0,%1,%2,%3};"
                 : "+f"(c[0]), "+f"(c[1]), "+f"(c[2]), "+f"(c[3])
                 : "r"(a[0]), "r"(a[1]), "r"(a[2]), "r"(a[3]), "r"(b[0]), "r"(b[1]));
}
__device__ __forceinline__ void cp16(unsigned dst, const void* src) {
    asm volatile("cp.async.cg.shared.global [%0], [%1], 16;" :: "r"(dst), "l"(src));
}
__device__ __forceinline__ void cp_commit() { asm volatile("cp.async.commit_group;"); }
__device__ __forceinline__ void cp_wait0()  { asm volatile("cp.async.wait_group 0;"); }

// ---------------- zero output + counters ----------------
__global__ void k_zero(float* __restrict__ out) {
    int idx = blockIdx.x * blockDim.x + threadIdx.x;
    ((float4*)out)[idx] = make_float4(0.f, 0.f, 0.f, 0.f);
    if (idx < E_) g_cnt[idx] = 0;
}

// ---------------- gating: warp per token ----------------
__global__ void k_gate(const float* __restrict__ x, const float* __restrict__ gw) {
    const int t    = blockIdx.x * 8 + (threadIdx.x >> 5);
    const int lane = threadIdx.x & 31;
    const float* xr = x + (size_t)t * D_;

    float p[E_];
#pragma unroll
    for (int e = 0; e < E_; e++) p[e] = 0.f;

    for (int d = lane * 4; d < D_; d += 128) {
        float4 xv = *(const float4*)(xr + d);
#pragma unroll
        for (int e = 0; e < E_; e++) {
            float4 gv = *(const float4*)(gw + e * D_ + d);
            p[e] += xv.x * gv.x + xv.y * gv.y + xv.z * gv.z + xv.w * gv.w;
        }
    }
#pragma unroll
    for (int o = 16; o; o >>= 1) {
#pragma unroll
        for (int e = 0; e < E_; e++) p[e] += __shfl_down_sync(0xffffffffu, p[e], o);
    }

    if (lane == 0) {
        float mx = p[0];
#pragma unroll
        for (int e = 1; e < E_; e++) mx = fmaxf(mx, p[e]);
        float pr[E_]; float den = 0.f;
#pragma unroll
        for (int e = 0; e < E_; e++) { pr[e] = expf(p[e] - mx); den += pr[e]; }
        float inv = 1.f / den;
#pragma unroll
        for (int e = 0; e < E_; e++) pr[e] *= inv;

        int e1 = 0;
#pragma unroll
        for (int e = 1; e < E_; e++) if (pr[e] > pr[e1]) e1 = e;
        int e2 = (e1 == 0) ? 1 : 0;
#pragma unroll
        for (int e = 0; e < E_; e++) if (e != e1 && pr[e] > pr[e2]) e2 = e;

        int i1 = atomicAdd(&g_cnt[e1], 1);
        g_tok[e1 * T_ + i1] = t; g_scr[e1 * T_ + i1] = pr[e1];
        int i2 = atomicAdd(&g_cnt[e2], 1);
        g_tok[e2 * T_ + i2] = t; g_scr[e2 * T_ + i2] = pr[e2];
    }
}

__global__ void k_prefix() {
    if (threadIdx.x == 0) {
        int s = 0;
#pragma unroll
        for (int e = 0; e < E_; e++) { g_off[e] = s; s += g_cnt[e]; }
    }
}

// Swizzles (engineered conflict-free for tf32 m16n8k8 fragment reads):
//   A smem [128][16]: kswz = (k + 4*((m>>1)&3)) & 15
//   B smem [16][128]: nswz = n ^ (8*(k&3))

// ---------------- GEMM1: h = silu(gather(X) @ w1[e]) ----------------
__global__ __launch_bounds__(256, 2) void k_ffn1(const float* __restrict__ x,
                                                 const float* __restrict__ w1) {
    const int e    = blockIdx.z;
    const int cnt  = g_cnt[e];
    const int row0 = blockIdx.y * 128;
    if (row0 >= cnt) return;
    const int n0b = blockIdx.x * 128;
    const int off = g_off[e];
    const float* Bw = w1 + (size_t)e * D_ * I_;

    __shared__ float As[2][128 * 16];
    __shared__ float Bs[2][16 * 128];

    const int tid = threadIdx.x;

    // ----- staging addresses -----
    const int rA  = tid >> 2;            // 0..63
    const int kcA = (tid & 3) * 4;
    const int gr0 = min(row0 + rA,      cnt - 1);
    const int gr1 = min(row0 + rA + 64, cnt - 1);
    const float* aS0 = x + (size_t)g_tok[e * T_ + gr0] * D_ + kcA;
    const float* aS1 = x + (size_t)g_tok[e * T_ + gr1] * D_ + kcA;
    const int rA1 = rA + 64;
    const unsigned aD0 = (unsigned)__cvta_generic_to_shared(
        &As[0][rA  * 16 + ((kcA + 4 * ((rA  >> 1) & 3)) & 15)]);
    const unsigned aD1 = (unsigned)__cvta_generic_to_shared(
        &As[0][rA1 * 16 + ((kcA + 4 * ((rA1 >> 1) & 3)) & 15)]);

    const int rB  = tid >> 5;            // 0..7
    const int ncB = (tid & 31) * 4;
    const float* bS0 = Bw + (size_t)rB * I_ + n0b + ncB;
    const float* bS1 = bS0 + (size_t)8 * I_;
    const unsigned bD0 = (unsigned)__cvta_generic_to_shared(
        &Bs[0][rB * 128 + (ncB ^ (8 * (rB & 3)))]);
    const unsigned bD1 = (unsigned)__cvta_generic_to_shared(
        &Bs[0][(rB + 8) * 128 + (ncB ^ (8 * (rB & 3)))]);

    const int wid = tid >> 5, lane = tid & 31;
    const int wm = wid & 3, wn = wid >> 2;
    const int qr = lane >> 2, qc = lane & 3;

    float c[2][8][4];
#pragma unroll
    for (int i = 0; i < 2; i++)
#pragma unroll
        for (int j = 0; j < 8; j++)
#pragma unroll
            for (int l = 0; l < 4; l++) c[i][j][l] = 0.f;

    // prologue
    cp16(aD0, aS0); cp16(aD1, aS1); cp16(bD0, bS0); cp16(bD1, bS1); cp_commit();

    const int KT = D_ / 16;   // 64
    for (int kt = 0; kt < KT; kt++) {
        cp_wait0();
        __syncthreads();
        if (kt + 1 < KT) {
            const int k0 = (kt + 1) * 16;
            const unsigned bo = ((kt + 1) & 1) * 8192;
            cp16(aD0 + bo, aS0 + k0);
            cp16(aD1 + bo, aS1 + k0);
            cp16(bD0 + bo, bS0 + (size_t)k0 * I_);
            cp16(bD1 + bo, bS1 + (size_t)k0 * I_);
            cp_commit();
        }
        const float* Ab = As[kt & 1];
        const float* Bb = Bs[kt & 1];
#pragma unroll
        for (int ks = 0; ks < 2; ks++) {
            const int kb = ks * 8 + qc;
            unsigned af[2][4];
#pragma unroll
            for (int mt = 0; mt < 2; mt++) {
                const int mlo = wm * 32 + mt * 16 + qr;
                const int mhi = mlo + 8;
                af[mt][0] = f2tf(Ab[mlo * 16 + ((kb     + 4 * ((mlo >> 1) & 3)) & 15)]);
                af[mt][1] = f2tf(Ab[mhi * 16 + ((kb     + 4 * ((mhi >> 1) & 3)) & 15)]);
                af[mt][2] = f2tf(Ab[mlo * 16 + ((kb + 4 + 4 * ((mlo >> 1) & 3)) & 15)]);
                af[mt][3] = f2tf(Ab[mhi * 16 + ((kb + 4 + 4 * ((mhi >> 1) & 3)) & 15)]);
            }
#pragma unroll
            for (int nt = 0; nt < 8; nt++) {
                const int n = wn * 64 + nt * 8 + qr;
                const unsigned sw = n ^ (8 * (kb & 3));
                unsigned bf[2];
                bf[0] = f2tf(Bb[kb * 128 + sw]);
                bf[1] = f2tf(Bb[(kb + 4) * 128 + sw]);
                mma_tf32(c[0][nt], af[0], bf);
                mma_tf32(c[1][nt], af[1], bf);
            }
        }
        __syncthreads();
    }

    // epilogue: silu -> g_h
#pragma unroll
    for (int mt = 0; mt < 2; mt++) {
        const int r = row0 + wm * 32 + mt * 16 + qr;
#pragma unroll
        for (int nt = 0; nt < 8; nt++) {
            const int n = n0b + wn * 64 + nt * 8 + 2 * qc;
            if (r < cnt) {
                float* p = g_h + (size_t)(off + r) * I_ + n;
                float v0 = c[mt][nt][0], v1 = c[mt][nt][1];
                p[0] = v0 / (1.f + expf(-v0));
                p[1] = v1 / (1.f + expf(-v1));
            }
            if (r + 8 < cnt) {
                float* p = g_h + (size_t)(off + r + 8) * I_ + n;
                float v2 = c[mt][nt][2], v3 = c[mt][nt][3];
                p[0] = v2 / (1.f + expf(-v2));
                p[1] = v3 / (1.f + expf(-v3));
            }
        }
    }
}

// ---------------- GEMM2: out[tok] += score * (h @ w2[e]) ----------------
__global__ __launch_bounds__(256, 2) void k_ffn2(const float* __restrict__ w2,
                                                 float* __restrict__ out) {
    const int e    = blockIdx.z;
    const int cnt  = g_cnt[e];
    const int row0 = blockIdx.y * 128;
    if (row0 >= cnt) return;
    const int n0b = blockIdx.x * 128;
    const int off = g_off[e];
    const float* Bw = w2 + (size_t)e * I_ * D_;

    __shared__ float As[2][128 * 16];
    __shared__ float Bs[2][16 * 128];

    const int tid = threadIdx.x;

    const int rA  = tid >> 2;
    const int kcA = (tid & 3) * 4;
    const int gr0 = min(row0 + rA,      cnt - 1);
    const int gr1 = min(row0 + rA + 64, cnt - 1);
    const float* aS0 = g_h + (size_t)(off + gr0) * I_ + kcA;
    const float* aS1 = g_h + (size_t)(off + gr1) * I_ + kcA;
    const int rA1 = rA + 64;
    const unsigned aD0 = (unsigned)__cvta_generic_to_shared(
        &As[0][rA  * 16 + ((kcA + 4 * ((rA  >> 1) & 3)) & 15)]);
    const unsigned aD1 = (unsigned)__cvta_generic_to_shared(
        &As[0][rA1 * 16 + ((kcA + 4 * ((rA1 >> 1) & 3)) & 15)]);

    const int rB  = tid >> 5;
    const int ncB = (tid & 31) * 4;
    const float* bS0 = Bw + (size_t)rB * D_ + n0b + ncB;
    const float* bS1 = bS0 + (size_t)8 * D_;
    const unsigned bD0 = (unsigned)__cvta_generic_to_shared(
        &Bs[0][rB * 128 + (ncB ^ (8 * (rB & 3)))]);
    const unsigned bD1 = (unsigned)__cvta_generic_to_shared(
        &Bs[0][(rB + 8) * 128 + (ncB ^ (8 * (rB & 3)))]);

    const int wid = tid >> 5, lane = tid & 31;
    const int wm = wid & 3, wn = wid >> 2;
    const int qr = lane >> 2, qc = lane & 3;

    float c[2][8][4];
#pragma unroll
    for (int i = 0; i < 2; i++)
#pragma unroll
        for (int j = 0; j < 8; j++)
#pragma unroll
            for (int l = 0; l < 4; l++) c[i][j][l] = 0.f;

    cp16(aD0, aS0); cp16(aD1, aS1); cp16(bD0, bS0); cp16(bD1, bS1); cp_commit();

    const int KT = I_ / 16;   // 128
    for (int kt = 0; kt < KT; kt++) {
        cp_wait0();
        __syncthreads();
        if (kt + 1 < KT) {
            const int k0 = (kt + 1) * 16;
            const unsigned bo = ((kt + 1) & 1) * 8192;
            cp16(aD0 + bo, aS0 + k0);
            cp16(aD1 + bo, aS1 + k0);
            cp16(bD0 + bo, bS0 + (size_t)k0 * D_);
            cp16(bD1 + bo, bS1 + (size_t)k0 * D_);
            cp_commit();
        }
        const float* Ab = As[kt & 1];
        const float* Bb = Bs[kt & 1];
#pragma unroll
        for (int ks = 0; ks < 2; ks++) {
            const int kb = ks * 8 + qc;
            unsigned af[2][4];
#pragma unroll
            for (int mt = 0; mt < 2; mt++) {
                const int mlo = wm * 32 + mt * 16 + qr;
                const int mhi = mlo + 8;
                af[mt][0] = f2tf(Ab[mlo * 16 + ((kb     + 4 * ((mlo >> 1) & 3)) & 15)]);
                af[mt][1] = f2tf(Ab[mhi * 16 + ((kb     + 4 * ((mhi >> 1) & 3)) & 15)]);
                af[mt][2] = f2tf(Ab[mlo * 16 + ((kb + 4 + 4 * ((mlo >> 1) & 3)) & 15)]);
                af[mt][3] = f2tf(Ab[mhi * 16 + ((kb + 4 + 4 * ((mhi >> 1) & 3)) & 15)]);
            }
#pragma unroll
            for (int nt = 0; nt < 8; nt++) {
                const int n = wn * 64 + nt * 8 + qr;
                const unsigned sw = n ^ (8 * (kb & 3));
                unsigned bf[2];
                bf[0] = f2tf(Bb[kb * 128 + sw]);
                bf[1] = f2tf(Bb[(kb + 4) * 128 + sw]);
                mma_tf32(c[0][nt], af[0], bf);
                mma_tf32(c[1][nt], af[1], bf);
            }
        }
        __syncthreads();
    }

    // epilogue: scaled atomic scatter
#pragma unroll
    for (int mt = 0; mt < 2; mt++) {
        const int r = row0 + wm * 32 + mt * 16 + qr;
        int   tok0 = 0, tok1 = 0; float s0 = 0.f, s1 = 0.f;
        const bool v0 = (r < cnt), v1 = (r + 8 < cnt);
        if (v0) { tok0 = g_tok[e * T_ + r];     s0 = g_scr[e * T_ + r]; }
        if (v1) { tok1 = g_tok[e * T_ + r + 8]; s1 = g_scr[e * T_ + r + 8]; }
#pragma unroll
        for (int nt = 0; nt < 8; nt++) {
            const int n = n0b + wn * 64 + nt * 8 + 2 * qc;
            if (v0) {
                float* p = out + (size_t)tok0 * D_ + n;
                atomicAdd(p,     s0 * c[mt][nt][0]);
                atomicAdd(p + 1, s0 * c[mt][nt][1]);
            }
            if (v1) {
                float* p = out + (size_t)tok1 * D_ + n;
                atomicAdd(p,     s1 * c[mt][nt][2]);
                atomicAdd(p + 1, s1 * c[mt][nt][3]);
            }
        }
    }
}

// ---------------- launch ----------------
extern "C" void kernel_launch(void* const* d_in, const int* in_sizes, int n_in,
                              void* d_out, int out_size) {
    const float* x  = (const float*)d_in[0];
    const float* gw = (const float*)d_in[1];
    const float* w1 = (const float*)d_in[2];
    const float* w2 = (const float*)d_in[3];
    float* out = (float*)d_out;

    k_zero<<<(T_ * D_ / 4) / 256, 256>>>(out);
    k_gate<<<T_ / 8, 256>>>(x, gw);
    k_prefix<<<1, 32>>>();
    k_ffn1<<<dim3(I_ / 128, T_ / 128, E_), 256>>>(x, w1);
    k_ffn2<<<dim3(D_ / 128, T_ / 128, E_), 256>>>(w2, out);
}